// round 2
// baseline (speedup 1.0000x reference)
#include <cuda_runtime.h>
#include <cstdint>
#include <cstddef>

// ---------------------------------------------------------------------------
// SelfAttention_68831145886674 : dual linear-attention branches + concat + 3x3 conv
// B=8, C=64, H=W=256, N=65536, KC=VC=64. Output fp32 [8,64,256,256].
//
// Decomposition per (branch, batch):
//   pass1: ksum[c]=sum_n Kn[c,n], vsum, M[k][v]=sum_n Kn[k,n]V[v,n]
//   prep : s=ksum+eps, u=r_w vsum, P=r_w M^T, G=P Wq, h=P bq
//   pass2: t=Wq x+bq ; y=G x+h ; inorm=1/||t|| ; d=1/(N + (t.s)*inorm)
//          cat[c] = d*u[c] + (d*inorm)*y[c] + r_b[c]
//   conv : 3x3 SAME, 128->64, + cat_b
// ---------------------------------------------------------------------------

#define NPIX 65536
#define EPSF 1e-6f

// ------------------------- device-global scratch ---------------------------
__device__ float g_part[2 * 8 * 64 * 4224];   // per-block partials (M,ksum,vsum)
__device__ float g_A2[16 * 8192];             // stacked [Wq; G] row-major [128][64]
__device__ float g_bias2[16 * 128];           // [bq; h]
__device__ float g_u[16 * 64];
__device__ float g_s[16 * 64];
__device__ float g_wt[73728];                 // conv w re-laid out [kk][ic][oc]
__device__ float g_cat[67108864ULL];          // [8][128][65536]

static __device__ __forceinline__ float rsqrt_acc(float x) {
    float r = rsqrtf(x);
    return r * (1.5f - 0.5f * x * r * r);
}

// ===========================================================================
// conv weight relayout: cat_w[oc][ic][ky][kx] -> g_wt[kk*8192 + ic*64 + oc]
// ===========================================================================
__global__ void wt_kernel(const float* __restrict__ cw) {
    int e = blockIdx.x * 256 + threadIdx.x;
    if (e < 73728) {
        int kk = e >> 13, rem = e & 8191, ic = rem >> 6, oc = rem & 63;
        g_wt[e] = cw[oc * 1152 + ic * 9 + kk];
    }
}

// ===========================================================================
// pass1: grid (64, 8, 2) x 256 thr. Block handles 1024 px (16 subtiles of 64).
// Computes partial M (4096), ksum (64), vsum (64) -> g_part.
// ===========================================================================
__global__ __launch_bounds__(256) void pass1_kernel(
    const float* __restrict__ x1, const float* __restrict__ x2,
    const float* __restrict__ k1w, const float* __restrict__ k1b,
    const float* __restrict__ v1w, const float* __restrict__ v1b,
    const float* __restrict__ k2w, const float* __restrict__ k2b,
    const float* __restrict__ v2w, const float* __restrict__ v2b)
{
    extern __shared__ float sm[];
    float* Ws  = sm;             // [64 c][132]  rows r=0..127 stacked [Wk;Wv]
    float* Xs  = Ws + 8448;      // [64 c][68]
    float* Ks  = Xs + 4352;      // [64 r][68]  normalized K tile
    float* Vs  = Ks + 4352;      // [64 r][68]
    float* bsm = Vs + 4352;      // [128]
    float* pn  = bsm + 128;      // [8][64]
    float* inv = pn + 512;       // [64]

    float4* Ws4 = reinterpret_cast<float4*>(Ws);
    float4* Xs4 = reinterpret_cast<float4*>(Xs);
    float4* Ks4 = reinterpret_cast<float4*>(Ks);
    float4* Vs4 = reinterpret_cast<float4*>(Vs);

    const int b = blockIdx.y, br = blockIdx.z;
    const float* x  = br ? x2  : x1;
    const float* kw = br ? k2w : k1w;
    const float* kb = br ? k2b : k1b;
    const float* vw = br ? v2w : v1w;
    const float* vb = br ? v2b : v1b;

    const int t  = threadIdx.x;
    const int tx = t & 15;
    const int ty = t >> 4;

    for (int e = t; e < 8192; e += 256) {
        int r = e >> 6, c = e & 63;
        Ws[c * 132 + r] = (r < 64) ? kw[r * 64 + c] : vw[(r - 64) * 64 + c];
    }
    if (t < 128) bsm[t] = (t < 64) ? kb[t] : vb[t - 64];
    __syncthreads();

    float Mreg[4][4];
#pragma unroll
    for (int i = 0; i < 4; ++i)
#pragma unroll
        for (int j = 0; j < 4; ++j) Mreg[i][j] = 0.f;
    float svacc = 0.f;

    const float* xb = x + (size_t)b * 64 * NPIX;
    const int pix0 = blockIdx.x * 1024;
    const int r0 = ty * 8;

    for (int st = 0; st < 16; ++st) {
        const int pb = pix0 + st * 64;
        __syncthreads();
        for (int e = t; e < 1024; e += 256) {
            int c = e >> 4, pq = e & 15;
            Xs4[c * 17 + pq] =
                *reinterpret_cast<const float4*>(xb + (size_t)c * NPIX + pb + pq * 4);
        }
        __syncthreads();

        float acc[8][4];
#pragma unroll
        for (int i = 0; i < 8; ++i)
#pragma unroll
            for (int j = 0; j < 4; ++j) acc[i][j] = 0.f;

#pragma unroll 4
        for (int c = 0; c < 64; ++c) {
            float4 a0 = Ws4[c * 33 + ty * 2];
            float4 a1 = Ws4[c * 33 + ty * 2 + 1];
            float4 bx = Xs4[c * 17 + tx];
            float av[8] = {a0.x, a0.y, a0.z, a0.w, a1.x, a1.y, a1.z, a1.w};
            float bv[4] = {bx.x, bx.y, bx.z, bx.w};
#pragma unroll
            for (int i = 0; i < 8; ++i)
#pragma unroll
                for (int j = 0; j < 4; ++j)
                    acc[i][j] = fmaf(av[i], bv[j], acc[i][j]);
        }
#pragma unroll
        for (int i = 0; i < 8; ++i) {
            float bb = bsm[r0 + i];
#pragma unroll
            for (int j = 0; j < 4; ++j) acc[i][j] += bb;
        }

        if (ty < 8) {
#pragma unroll
            for (int j = 0; j < 4; ++j) {
                float s = 0.f;
#pragma unroll
                for (int i = 0; i < 8; ++i) s = fmaf(acc[i][j], acc[i][j], s);
                pn[ty * 64 + tx * 4 + j] = s;
            }
        }
        __syncthreads();
        if (t < 64) {
            float s = 0.f;
#pragma unroll
            for (int g = 0; g < 8; ++g) s += pn[g * 64 + t];
            inv[t] = rsqrt_acc(s);
        }
        __syncthreads();
        if (ty < 8) {
            float i0 = inv[tx * 4], i1 = inv[tx * 4 + 1], i2 = inv[tx * 4 + 2], i3 = inv[tx * 4 + 3];
#pragma unroll
            for (int i = 0; i < 8; ++i) {
                float4 o;
                o.x = acc[i][0] * i0; o.y = acc[i][1] * i1;
                o.z = acc[i][2] * i2; o.w = acc[i][3] * i3;
                Ks4[(r0 + i) * 17 + tx] = o;
            }
        } else {
#pragma unroll
            for (int i = 0; i < 8; ++i) {
                float4 o;
                o.x = acc[i][0]; o.y = acc[i][1]; o.z = acc[i][2]; o.w = acc[i][3];
                Vs4[(r0 - 64 + i) * 17 + tx] = o;
            }
        }
        __syncthreads();

        // ksum / vsum partials
        if (t < 128) {
            const float4* row = (t < 64) ? &Ks4[t * 17] : &Vs4[(t - 64) * 17];
#pragma unroll
            for (int pq = 0; pq < 16; ++pq) {
                float4 v = row[pq];
                svacc += (v.x + v.y) + (v.z + v.w);
            }
        }

        // M += Kn * V^T over this 64-px subtile
#pragma unroll 2
        for (int pq = 0; pq < 16; ++pq) {
            float4 a[4], bq4[4];
#pragma unroll
            for (int r = 0; r < 4; ++r) a[r]   = Ks4[(ty * 4 + r) * 17 + pq];
#pragma unroll
            for (int r = 0; r < 4; ++r) bq4[r] = Vs4[(tx * 4 + r) * 17 + pq];
#pragma unroll
            for (int i = 0; i < 4; ++i)
#pragma unroll
                for (int j = 0; j < 4; ++j) {
                    Mreg[i][j] = fmaf(a[i].x, bq4[j].x, Mreg[i][j]);
                    Mreg[i][j] = fmaf(a[i].y, bq4[j].y, Mreg[i][j]);
                    Mreg[i][j] = fmaf(a[i].z, bq4[j].z, Mreg[i][j]);
                    Mreg[i][j] = fmaf(a[i].w, bq4[j].w, Mreg[i][j]);
                }
        }
    }

    float* dst = g_part + ((size_t)(br * 8 + b) * 64 + blockIdx.x) * 4224;
    float4* dst4 = reinterpret_cast<float4*>(dst);
#pragma unroll
    for (int i = 0; i < 4; ++i) {
        float4 o;
        o.x = Mreg[i][0]; o.y = Mreg[i][1]; o.z = Mreg[i][2]; o.w = Mreg[i][3];
        dst4[(ty * 4 + i) * 16 + tx] = o;
    }
    if (t < 128) dst[4096 + t] = svacc;
}

// ===========================================================================
// prep: grid 16 (br*8+b) x 256. Reduce partials, build A2=[Wq;G], bias2, u, s.
// ===========================================================================
__global__ __launch_bounds__(256) void prep_kernel(
    const float* __restrict__ q1w, const float* __restrict__ q1b, const float* __restrict__ r1w,
    const float* __restrict__ q2w, const float* __restrict__ q2b, const float* __restrict__ r2w)
{
    __shared__ float Ms[64 * 68];
    __shared__ float Ps[64 * 68];
    __shared__ float ks[64];
    __shared__ float vs[64];

    const int id = blockIdx.x;
    const int br = id >> 3;
    const float* qw = br ? q2w : q1w;
    const float* qb = br ? q2b : q1b;
    const float* rw = br ? r2w : r1w;
    const float* src = g_part + (size_t)id * 64 * 4224;
    const int t = threadIdx.x;

    for (int e = t; e < 4224; e += 256) {
        float s = 0.f;
        for (int blk = 0; blk < 64; ++blk) s += src[(size_t)blk * 4224 + e];
        if (e < 4096)      Ms[(e >> 6) * 68 + (e & 63)] = s;
        else if (e < 4160) ks[e - 4096] = s;
        else               vs[e - 4160] = s;
    }
    __syncthreads();

    // P[o][k] = sum_v rw[o][v] * M[k][v]
    for (int e = t; e < 4096; e += 256) {
        int o = e >> 6, k = e & 63;
        float s = 0.f;
        for (int v = 0; v < 64; ++v) s = fmaf(rw[o * 64 + v], Ms[k * 68 + v], s);
        Ps[o * 68 + k] = s;
    }
    __syncthreads();

    float* A2 = g_A2 + (size_t)id * 8192;
    for (int e = t; e < 4096; e += 256) {
        int o = e >> 6, c = e & 63;
        float g = 0.f;
        for (int k = 0; k < 64; ++k) g = fmaf(Ps[o * 68 + k], qw[k * 64 + c], g);
        A2[(64 + o) * 64 + c] = g;
        A2[o * 64 + c] = qw[o * 64 + c];
    }
    if (t < 64) {
        float u = 0.f, h = 0.f;
        for (int v = 0; v < 64; ++v) u = fmaf(rw[t * 64 + v], vs[v], u);
        for (int k = 0; k < 64; ++k) h = fmaf(Ps[t * 68 + k], qb[k], h);
        g_u[id * 64 + t] = u;
        g_s[id * 64 + t] = ks[t] + EPSF;
        g_bias2[id * 128 + t] = qb[t];
        g_bias2[id * 128 + 64 + t] = h;
    }
}

// ===========================================================================
// pass2: grid (64, 8, 2) x 256. Per pixel: z = A2 x + bias2 (128 rows),
// epilogue builds cat channels. Writes g_cat[b][br*64+c][px].
// ===========================================================================
__global__ __launch_bounds__(256) void pass2_kernel(
    const float* __restrict__ x1, const float* __restrict__ x2,
    const float* __restrict__ r1b, const float* __restrict__ r2b)
{
    extern __shared__ float sm[];
    float* As  = sm;             // [64 c][132]
    float* Xs  = As + 8448;      // [64 c][68]
    float* pn  = Xs + 4352;      // [8][64]
    float* pd  = pn + 512;       // [8][64]
    float* fA  = pd + 512;       // [64]
    float* fB  = fA + 64;        // [64]
    float* bsm = fB + 64;        // [128]
    float* us  = bsm + 128;      // [64]
    float* ss  = us + 64;        // [64]
    float* rbs = ss + 64;        // [64]

    float4* As4 = reinterpret_cast<float4*>(As);
    float4* Xs4 = reinterpret_cast<float4*>(Xs);

    const int b = blockIdx.y, br = blockIdx.z;
    const int id = br * 8 + b;
    const float* x  = br ? x2  : x1;
    const float* rb = br ? r2b : r1b;

    const int t  = threadIdx.x;
    const int tx = t & 15;
    const int ty = t >> 4;
    const int r0 = ty * 8;

    const float* A2 = g_A2 + (size_t)id * 8192;
    for (int e = t; e < 8192; e += 256) {
        int r = e >> 6, c = e & 63;
        As[c * 132 + r] = A2[e];
    }
    if (t < 128) bsm[t] = g_bias2[id * 128 + t];
    if (t < 64) {
        us[t]  = g_u[id * 64 + t];
        ss[t]  = g_s[id * 64 + t];
        rbs[t] = rb[t];
    }
    __syncthreads();

    const float* xb = x + (size_t)b * 64 * NPIX;
    float* catb = g_cat + ((size_t)b * 128 + (size_t)br * 64) * NPIX;
    const int pix0 = blockIdx.x * 1024;

    for (int st = 0; st < 16; ++st) {
        const int pb = pix0 + st * 64;
        __syncthreads();
        for (int e = t; e < 1024; e += 256) {
            int c = e >> 4, pq = e & 15;
            Xs4[c * 17 + pq] =
                *reinterpret_cast<const float4*>(xb + (size_t)c * NPIX + pb + pq * 4);
        }
        __syncthreads();

        float acc[8][4];
#pragma unroll
        for (int i = 0; i < 8; ++i)
#pragma unroll
            for (int j = 0; j < 4; ++j) acc[i][j] = 0.f;

#pragma unroll 4
        for (int c = 0; c < 64; ++c) {
            float4 a0 = As4[c * 33 + ty * 2];
            float4 a1 = As4[c * 33 + ty * 2 + 1];
            float4 bx = Xs4[c * 17 + tx];
            float av[8] = {a0.x, a0.y, a0.z, a0.w, a1.x, a1.y, a1.z, a1.w};
            float bv[4] = {bx.x, bx.y, bx.z, bx.w};
#pragma unroll
            for (int i = 0; i < 8; ++i)
#pragma unroll
                for (int j = 0; j < 4; ++j)
                    acc[i][j] = fmaf(av[i], bv[j], acc[i][j]);
        }
#pragma unroll
        for (int i = 0; i < 8; ++i) {
            float bb = bsm[r0 + i];
#pragma unroll
            for (int j = 0; j < 4; ++j) acc[i][j] += bb;
        }

        if (ty < 8) {
#pragma unroll
            for (int j = 0; j < 4; ++j) {
                float sn = 0.f, sd = 0.f;
#pragma unroll
                for (int i = 0; i < 8; ++i) {
                    float v = acc[i][j];
                    sn = fmaf(v, v, sn);
                    sd = fmaf(v, ss[r0 + i], sd);
                }
                pn[ty * 64 + tx * 4 + j] = sn;
                pd[ty * 64 + tx * 4 + j] = sd;
            }
        }
        __syncthreads();
        if (t < 64) {
            float sn = 0.f, sd = 0.f;
#pragma unroll
            for (int g = 0; g < 8; ++g) { sn += pn[g * 64 + t]; sd += pd[g * 64 + t]; }
            float inorm = rsqrt_acc(sn);
            float d = 1.0f / (65536.0f + sd * inorm);
            fA[t] = d;
            fB[t] = d * inorm;
        }
        __syncthreads();
        if (ty >= 8) {
            float a0 = fA[tx * 4], a1 = fA[tx * 4 + 1], a2 = fA[tx * 4 + 2], a3 = fA[tx * 4 + 3];
            float b0 = fB[tx * 4], b1 = fB[tx * 4 + 1], b2 = fB[tx * 4 + 2], b3 = fB[tx * 4 + 3];
#pragma unroll
            for (int i = 0; i < 8; ++i) {
                int c = r0 - 64 + i;
                float uc = us[c], rc = rbs[c];
                float4 o;
                o.x = fmaf(b0, acc[i][0], fmaf(a0, uc, rc));
                o.y = fmaf(b1, acc[i][1], fmaf(a1, uc, rc));
                o.z = fmaf(b2, acc[i][2], fmaf(a2, uc, rc));
                o.w = fmaf(b3, acc[i][3], fmaf(a3, uc, rc));
                *reinterpret_cast<float4*>(catb + (size_t)c * NPIX + pb + tx * 4) = o;
            }
        }
    }
}

// ===========================================================================
// conv: 3x3 SAME 128->64. grid (16, 64, 8) x 256. Block: 64 oc x (16w x 4h).
// Thread: 4 oc x 4 y at one x. smem: weights chunk [9][16][64] + input halo.
// ===========================================================================
__global__ __launch_bounds__(256) void conv_kernel(
    const float* __restrict__ cb, float* __restrict__ out)
{
    __shared__ float ws[9216];   // [(kk*16+ic)*64 + oc]
    __shared__ float is[1728];   // [ic][6][18]

    const int x0 = blockIdx.x * 16;
    const int y0 = blockIdx.y * 4;
    const int b  = blockIdx.z;
    const int t  = threadIdx.x;
    const int pxg = t & 15;
    const int ocg = t >> 4;

    float acc[4][4];
#pragma unroll
    for (int i = 0; i < 4; ++i)
#pragma unroll
        for (int j = 0; j < 4; ++j) acc[i][j] = 0.f;

    const float* catb = g_cat + (size_t)b * 128 * NPIX;

    for (int ch = 0; ch < 8; ++ch) {
        const int ic0 = ch * 16;
        __syncthreads();
        for (int e = t; e < 9216; e += 256) {
            int kk = e >> 10, rem = e & 1023;
            ws[e] = g_wt[(size_t)kk * 8192 + (size_t)(ic0 << 6) + rem];
        }
        for (int e = t; e < 1728; e += 256) {
            int ic = e / 108, rem = e - ic * 108;
            int yy = rem / 18, xx = rem - yy * 18;
            int gy = y0 - 1 + yy, gx = x0 - 1 + xx;
            float v = 0.f;
            if ((unsigned)gy < 256u && (unsigned)gx < 256u)
                v = catb[((size_t)(ic0 + ic) << 16) + gy * 256 + gx];
            is[e] = v;
        }
        __syncthreads();

#pragma unroll 2
        for (int ic = 0; ic < 16; ++ic) {
            float rin[6][3];
            const float* ib = &is[ic * 108 + pxg];
#pragma unroll
            for (int rr = 0; rr < 6; ++rr)
#pragma unroll
                for (int dx = 0; dx < 3; ++dx)
                    rin[rr][dx] = ib[rr * 18 + dx];
#pragma unroll
            for (int ky = 0; ky < 3; ++ky)
#pragma unroll
                for (int kx = 0; kx < 3; ++kx) {
                    float4 w = *reinterpret_cast<const float4*>(
                        &ws[((ky * 3 + kx) * 16 + ic) * 64 + ocg * 4]);
#pragma unroll
                    for (int yy = 0; yy < 4; ++yy) {
                        float iv = rin[yy + ky][kx];
                        acc[0][yy] = fmaf(w.x, iv, acc[0][yy]);
                        acc[1][yy] = fmaf(w.y, iv, acc[1][yy]);
                        acc[2][yy] = fmaf(w.z, iv, acc[2][yy]);
                        acc[3][yy] = fmaf(w.w, iv, acc[3][yy]);
                    }
                }
        }
    }

#pragma unroll
    for (int i = 0; i < 4; ++i) {
        int oc = ocg * 4 + i;
        float bias = cb[oc];
#pragma unroll
        for (int yy = 0; yy < 4; ++yy)
            out[((size_t)(b * 64 + oc) << 16) + (size_t)(y0 + yy) * 256 + x0 + pxg] =
                acc[i][yy] + bias;
    }
}

// ===========================================================================
extern "C" void kernel_launch(void* const* d_in, const int* in_sizes, int n_in,
                              void* d_out, int out_size)
{
    (void)in_sizes; (void)n_in; (void)out_size;
    const float* t1  = (const float*)d_in[0];
    const float* t2  = (const float*)d_in[1];
    const float* q1w = (const float*)d_in[2];
    const float* q1b = (const float*)d_in[3];
    const float* k1w = (const float*)d_in[4];
    const float* k1b = (const float*)d_in[5];
    const float* v1w = (const float*)d_in[6];
    const float* v1b = (const float*)d_in[7];
    const float* r1w = (const float*)d_in[8];
    const float* r1b = (const float*)d_in[9];
    const float* q2w = (const float*)d_in[10];
    const float* q2b = (const float*)d_in[11];
    const float* k2w = (const float*)d_in[12];
    const float* k2b = (const float*)d_in[13];
    const float* v2w = (const float*)d_in[14];
    const float* v2b = (const float*)d_in[15];
    const float* r2w = (const float*)d_in[16];
    const float* r2b = (const float*)d_in[17];
    const float* cw  = (const float*)d_in[18];
    const float* cbp = (const float*)d_in[19];
    float* out = (float*)d_out;

    cudaFuncSetAttribute(pass1_kernel, cudaFuncAttributeMaxDynamicSharedMemorySize, 90 * 1024);
    cudaFuncSetAttribute(pass2_kernel, cudaFuncAttributeMaxDynamicSharedMemorySize, 60 * 1024);

    wt_kernel<<<288, 256>>>(cw);
    pass1_kernel<<<dim3(64, 8, 2), 256, 88832>>>(t1, t2, k1w, k1b, v1w, v1b,
                                                 k2w, k2b, v2w, v2b);
    prep_kernel<<<16, 256>>>(q1w, q1b, r1w, q2w, q2b, r2w);
    pass2_kernel<<<dim3(64, 8, 2), 256, 57088>>>(t1, t2, r1b, r2b);
    conv_kernel<<<dim3(16, 64, 8), 256>>>(cbp, out);
}

// round 5
// speedup vs baseline: 1.0244x; 1.0244x over previous
#include <cuda_runtime.h>
#include <cstdint>
#include <cstddef>

// ---------------------------------------------------------------------------
// SelfAttention_68831145886674 : dual linear-attention branches + concat + 3x3 conv
// B=8, C=64, H=W=256, N=65536, KC=VC=64. Output fp32 [8,64,256,256].
// All hot loops use packed fma.rn.f32x2 (FFMA2), packed along the reduction dim
// so operand pairs come free from 64/128-bit shared loads (no packing movs).
// ---------------------------------------------------------------------------

#define NPIX 65536
#define EPSF 1e-6f

typedef unsigned long long u64;

// ------------------------- device-global scratch ---------------------------
__device__ float g_part[2 * 8 * 64 * 4224];   // per-block partials (M,ksum,vsum)
__device__ float g_A2[16 * 8192];             // stacked [Wq; G] row-major [128][64]
__device__ float g_bias2[16 * 128];           // [bq; h]
__device__ float g_u[16 * 64];
__device__ float g_s[16 * 64];
__device__ float g_wt[73728];                 // conv w: [kk][icp][oc][2]
__device__ float g_cat[67108864ULL];          // [8][128][65536]

static __device__ __forceinline__ void fma2(u64& d, u64 a, u64 b) {
    asm("fma.rn.f32x2 %0, %1, %2, %0;" : "+l"(d) : "l"(a), "l"(b));
}
static __device__ __forceinline__ float hsum2(u64 v) {
    float lo, hi;
    asm("mov.b64 {%0,%1}, %2;" : "=f"(lo), "=f"(hi) : "l"(v));
    return lo + hi;
}
static __device__ __forceinline__ float rsqrt_acc(float x) {
    float r = rsqrtf(x);
    return r * (1.5f - 0.5f * x * r * r);
}

// ===========================================================================
// conv weight relayout: cat_w[oc][ic][ky][kx] -> g_wt[kk*8192 + icp*128 + oc*2 + par]
// (ic = icp*2 + par)
// ===========================================================================
__global__ void wt_kernel(const float* __restrict__ cw) {
    int e = blockIdx.x * 256 + threadIdx.x;
    if (e < 73728) {
        int kk = e / 8192, rem = e & 8191;
        int icp = rem >> 7, oc2 = rem & 127, oc = oc2 >> 1, par = oc2 & 1;
        g_wt[e] = cw[oc * 1152 + (icp * 2 + par) * 9 + kk];
    }
}

// ===========================================================================
// pass1: grid (64, 8, 2) x 256 thr. Block handles 1024 px (16 subtiles of 64).
// Computes partial M (4096), ksum (64), vsum (64) -> g_part.
// ===========================================================================
__global__ __launch_bounds__(256) void pass1_kernel(
    const float* __restrict__ x1, const float* __restrict__ x2,
    const float* __restrict__ k1w, const float* __restrict__ k1b,
    const float* __restrict__ v1w, const float* __restrict__ v1b,
    const float* __restrict__ k2w, const float* __restrict__ k2b,
    const float* __restrict__ v2w, const float* __restrict__ v2b)
{
    extern __shared__ float sm[];
    float* Wp  = sm;             // 32*264 = 8448  (c-interleaved [Wk;Wv])
    float* Xp  = Wp + 8448;      // 32*132 = 4224  (c-interleaved x tile)
    float* Ks  = Xp + 4224;      // 64*68  = 4352
    float* Vs  = Ks + 4352;      // 64*68  = 4352
    float* bsm = Vs + 4352;      // 128
    float* pn  = bsm + 128;      // 512
    float* inv = pn + 512;       // 64

    const int b = blockIdx.y, br = blockIdx.z;
    const float* x  = br ? x2  : x1;
    const float* kw = br ? k2w : k1w;
    const float* kb = br ? k2b : k1b;
    const float* vw = br ? v2w : v1w;
    const float* vb = br ? v2b : v1b;

    const int t  = threadIdx.x;
    const int tx = t & 15;
    const int ty = t >> 4;
    const int r0 = ty * 8;

    // stacked [Wk;Wv], c-interleaved: Wp[(c>>1)*264 + r*2 + (c&1)]
    for (int e = t; e < 8192; e += 256) {
        int r = e >> 6, c = e & 63;
        float w = (r < 64) ? kw[r * 64 + c] : vw[(r - 64) * 64 + c];
        Wp[(c >> 1) * 264 + r * 2 + (c & 1)] = w;
    }
    if (t < 128) bsm[t] = (t < 64) ? kb[t] : vb[t - 64];
    __syncthreads();

    u64 M2[4][4];
#pragma unroll
    for (int i = 0; i < 4; ++i)
#pragma unroll
        for (int j = 0; j < 4; ++j) M2[i][j] = 0ULL;
    float svacc = 0.f;

    const float* xb = x + (size_t)b * 64 * NPIX;
    const int pix0 = blockIdx.x * 1024;

    for (int st = 0; st < 16; ++st) {
        const int pb = pix0 + st * 64;
        __syncthreads();
        // fill Xp c-interleaved: Xp[(c>>1)*132 + px*2 + (c&1)]
        for (int e = t; e < 1024; e += 256) {
            int c = e >> 4, pq = e & 15;
            float4 v = *reinterpret_cast<const float4*>(xb + (size_t)c * NPIX + pb + pq * 4);
            float* d = Xp + (c >> 1) * 132 + (c & 1) + pq * 8;
            d[0] = v.x; d[2] = v.y; d[4] = v.z; d[6] = v.w;
        }
        __syncthreads();

        // GEMM: rows r0..r0+7 (stacked K/V), px = tx+16j. Packed over c.
        u64 acc2[8][4];
#pragma unroll
        for (int i = 0; i < 8; ++i)
#pragma unroll
            for (int j = 0; j < 4; ++j) acc2[i][j] = 0ULL;

#pragma unroll 2
        for (int cp = 0; cp < 32; ++cp) {
            const ulonglong2* wa =
                reinterpret_cast<const ulonglong2*>(Wp + cp * 264 + r0 * 2);
            ulonglong2 A0 = wa[0], A1 = wa[1], A2v = wa[2], A3 = wa[3];
            u64 av[8] = {A0.x, A0.y, A1.x, A1.y, A2v.x, A2v.y, A3.x, A3.y};
            const float* xr = Xp + cp * 132 + tx * 2;
            u64 bv[4];
            bv[0] = *reinterpret_cast<const u64*>(xr);
            bv[1] = *reinterpret_cast<const u64*>(xr + 32);
            bv[2] = *reinterpret_cast<const u64*>(xr + 64);
            bv[3] = *reinterpret_cast<const u64*>(xr + 96);
#pragma unroll
            for (int i = 0; i < 8; ++i)
#pragma unroll
                for (int j = 0; j < 4; ++j) fma2(acc2[i][j], av[i], bv[j]);
        }

        float accs[8][4];
#pragma unroll
        for (int i = 0; i < 8; ++i) {
            float bb = bsm[r0 + i];
#pragma unroll
            for (int j = 0; j < 4; ++j) accs[i][j] = hsum2(acc2[i][j]) + bb;
        }

        // K-norm partial sums (rows 0..63 live in ty<8)
        if (ty < 8) {
#pragma unroll
            for (int j = 0; j < 4; ++j) {
                float s = 0.f;
#pragma unroll
                for (int i = 0; i < 8; ++i) s = fmaf(accs[i][j], accs[i][j], s);
                pn[ty * 64 + tx + 16 * j] = s;
            }
        }
        __syncthreads();
        if (t < 64) {
            float s = 0.f;
#pragma unroll
            for (int g = 0; g < 8; ++g) s += pn[g * 64 + t];
            inv[t] = rsqrt_acc(s);
        }
        __syncthreads();
        if (ty < 8) {
            float iv0 = inv[tx], iv1 = inv[tx + 16], iv2 = inv[tx + 32], iv3 = inv[tx + 48];
#pragma unroll
            for (int i = 0; i < 8; ++i) {
                float* row = Ks + (r0 + i) * 68 + tx;
                row[0]  = accs[i][0] * iv0;
                row[16] = accs[i][1] * iv1;
                row[32] = accs[i][2] * iv2;
                row[48] = accs[i][3] * iv3;
            }
        } else {
#pragma unroll
            for (int i = 0; i < 8; ++i) {
                float* row = Vs + (r0 - 64 + i) * 68 + tx;
                row[0]  = accs[i][0];
                row[16] = accs[i][1];
                row[32] = accs[i][2];
                row[48] = accs[i][3];
            }
        }
        __syncthreads();

        // ksum / vsum partials
        if (t < 128) {
            const float4* row = (t < 64)
                ? reinterpret_cast<const float4*>(Ks + t * 68)
                : reinterpret_cast<const float4*>(Vs + (t - 64) * 68);
#pragma unroll
            for (int pq = 0; pq < 16; ++pq) {
                float4 v = row[pq];
                svacc += (v.x + v.y) + (v.z + v.w);
            }
        }

        // M[k][v] += Kn * V^T ; k = ty*4+i, v = tx+16j ; packed over px
#pragma unroll 2
        for (int p4 = 0; p4 < 16; ++p4) {
            ulonglong2 a[4], bb[4];
#pragma unroll
            for (int r = 0; r < 4; ++r)
                a[r] = *reinterpret_cast<const ulonglong2*>(Ks + (ty * 4 + r) * 68 + p4 * 4);
#pragma unroll
            for (int r = 0; r < 4; ++r)
                bb[r] = *reinterpret_cast<const ulonglong2*>(Vs + (tx + 16 * r) * 68 + p4 * 4);
#pragma unroll
            for (int i = 0; i < 4; ++i)
#pragma unroll
                for (int j = 0; j < 4; ++j) {
                    fma2(M2[i][j], a[i].x, bb[j].x);
                    fma2(M2[i][j], a[i].y, bb[j].y);
                }
        }
    }

    float* dst = g_part + ((size_t)(br * 8 + b) * 64 + blockIdx.x) * 4224;
#pragma unroll
    for (int i = 0; i < 4; ++i)
#pragma unroll
        for (int j = 0; j < 4; ++j)
            dst[(ty * 4 + i) * 64 + tx + 16 * j] = hsum2(M2[i][j]);
    if (t < 128) dst[4096 + t] = svacc;
}

// ===========================================================================
// prep: grid 16 (br*8+b) x 256. Reduce partials, build A2=[Wq;G], bias2, u, s.
// ===========================================================================
__global__ __launch_bounds__(256) void prep_kernel(
    const float* __restrict__ q1w, const float* __restrict__ q1b, const float* __restrict__ r1w,
    const float* __restrict__ q2w, const float* __restrict__ q2b, const float* __restrict__ r2w)
{
    __shared__ float Ms[64 * 68];
    __shared__ float Ps[64 * 68];
    __shared__ float ks[64];
    __shared__ float vs[64];

    const int id = blockIdx.x;
    const int br = id >> 3;
    const float* qw = br ? q2w : q1w;
    const float* qb = br ? q2b : q1b;
    const float* rw = br ? r2w : r1w;
    const float* src = g_part + (size_t)id * 64 * 4224;
    const int t = threadIdx.x;

    for (int e = t; e < 4224; e += 256) {
        float s = 0.f;
        for (int blk = 0; blk < 64; ++blk) s += src[(size_t)blk * 4224 + e];
        if (e < 4096)      Ms[(e >> 6) * 68 + (e & 63)] = s;
        else if (e < 4160) ks[e - 4096] = s;
        else               vs[e - 4160] = s;
    }
    __syncthreads();

    // P[o][k] = sum_v rw[o][v] * M[k][v]
    for (int e = t; e < 4096; e += 256) {
        int o = e >> 6, k = e & 63;
        float s = 0.f;
        for (int v = 0; v < 64; ++v) s = fmaf(rw[o * 64 + v], Ms[k * 68 + v], s);
        Ps[o * 68 + k] = s;
    }
    __syncthreads();

    float* A2 = g_A2 + (size_t)id * 8192;
    for (int e = t; e < 4096; e += 256) {
        int o = e >> 6, c = e & 63;
        float g = 0.f;
        for (int k = 0; k < 64; ++k) g = fmaf(Ps[o * 68 + k], qw[k * 64 + c], g);
        A2[(64 + o) * 64 + c] = g;
        A2[o * 64 + c] = qw[o * 64 + c];
    }
    if (t < 64) {
        float u = 0.f, h = 0.f;
        for (int v = 0; v < 64; ++v) u = fmaf(rw[t * 64 + v], vs[v], u);
        for (int k = 0; k < 64; ++k) h = fmaf(Ps[t * 68 + k], qb[k], h);
        g_u[id * 64 + t] = u;
        g_s[id * 64 + t] = ks[t] + EPSF;
        g_bias2[id * 128 + t] = qb[t];
        g_bias2[id * 128 + 64 + t] = h;
    }
}

// ===========================================================================
// pass2: grid (64, 8, 2) x 256. Per pixel: z = A2 x + bias2 (128 rows),
// epilogue builds cat channels. Writes g_cat[b][br*64+c][px].
// ===========================================================================
__global__ __launch_bounds__(256) void pass2_kernel(
    const float* __restrict__ x1, const float* __restrict__ x2,
    const float* __restrict__ r1b, const float* __restrict__ r2b)
{
    extern __shared__ float sm[];
    float* Wp  = sm;             // 8448
    float* Xp  = Wp + 8448;      // 4224
    float* pn  = Xp + 4224;      // 512
    float* pd  = pn + 512;       // 512
    float* fA  = pd + 512;       // 64
    float* fB  = fA + 64;        // 64
    float* bsm = fB + 64;        // 128
    float* us  = bsm + 128;      // 64
    float* ss  = us + 64;        // 64
    float* rbs = ss + 64;        // 64

    const int b = blockIdx.y, br = blockIdx.z;
    const int id = br * 8 + b;
    const float* x  = br ? x2  : x1;
    const float* rb = br ? r2b : r1b;

    const int t  = threadIdx.x;
    const int tx = t & 15;
    const int ty = t >> 4;
    const int r0 = ty * 8;

    const float* A2 = g_A2 + (size_t)id * 8192;
    for (int e = t; e < 8192; e += 256) {
        int r = e >> 6, c = e & 63;
        Wp[(c >> 1) * 264 + r * 2 + (c & 1)] = A2[e];
    }
    if (t < 128) bsm[t] = g_bias2[id * 128 + t];
    if (t < 64) {
        us[t]  = g_u[id * 64 + t];
        ss[t]  = g_s[id * 64 + t];
        rbs[t] = rb[t];
    }
    __syncthreads();

    const float* xb = x + (size_t)b * 64 * NPIX;
    float* catb = g_cat + ((size_t)b * 128 + (size_t)br * 64) * NPIX;
    const int pix0 = blockIdx.x * 1024;

    for (int st = 0; st < 16; ++st) {
        const int pb = pix0 + st * 64;
        __syncthreads();
        for (int e = t; e < 1024; e += 256) {
            int c = e >> 4, pq = e & 15;
            float4 v = *reinterpret_cast<const float4*>(xb + (size_t)c * NPIX + pb + pq * 4);
            float* d = Xp + (c >> 1) * 132 + (c & 1) + pq * 8;
            d[0] = v.x; d[2] = v.y; d[4] = v.z; d[6] = v.w;
        }
        __syncthreads();

        u64 acc2[8][4];
#pragma unroll
        for (int i = 0; i < 8; ++i)
#pragma unroll
            for (int j = 0; j < 4; ++j) acc2[i][j] = 0ULL;

#pragma unroll 2
        for (int cp = 0; cp < 32; ++cp) {
            const ulonglong2* wa =
                reinterpret_cast<const ulonglong2*>(Wp + cp * 264 + r0 * 2);
            ulonglong2 A0 = wa[0], A1 = wa[1], A2v = wa[2], A3 = wa[3];
            u64 av[8] = {A0.x, A0.y, A1.x, A1.y, A2v.x, A2v.y, A3.x, A3.y};
            const float* xr = Xp + cp * 132 + tx * 2;
            u64 bv[4];
            bv[0] = *reinterpret_cast<const u64*>(xr);
            bv[1] = *reinterpret_cast<const u64*>(xr + 32);
            bv[2] = *reinterpret_cast<const u64*>(xr + 64);
            bv[3] = *reinterpret_cast<const u64*>(xr + 96);
#pragma unroll
            for (int i = 0; i < 8; ++i)
#pragma unroll
                for (int j = 0; j < 4; ++j) fma2(acc2[i][j], av[i], bv[j]);
        }

        float accs[8][4];
#pragma unroll
        for (int i = 0; i < 8; ++i) {
            float bb = bsm[r0 + i];
#pragma unroll
            for (int j = 0; j < 4; ++j) accs[i][j] = hsum2(acc2[i][j]) + bb;
        }

        if (ty < 8) {
#pragma unroll
            for (int j = 0; j < 4; ++j) {
                float sn = 0.f, sd = 0.f;
#pragma unroll
                for (int i = 0; i < 8; ++i) {
                    float v = accs[i][j];
                    sn = fmaf(v, v, sn);
                    sd = fmaf(v, ss[r0 + i], sd);
                }
                pn[ty * 64 + tx + 16 * j] = sn;
                pd[ty * 64 + tx + 16 * j] = sd;
            }
        }
        __syncthreads();
        if (t < 64) {
            float sn = 0.f, sd = 0.f;
#pragma unroll
            for (int g = 0; g < 8; ++g) { sn += pn[g * 64 + t]; sd += pd[g * 64 + t]; }
            float inorm = rsqrt_acc(sn);
            float d = 1.0f / (65536.0f + sd * inorm);
            fA[t] = d;
            fB[t] = d * inorm;
        }
        __syncthreads();
        if (ty >= 8) {
            float a0 = fA[tx], a1 = fA[tx + 16], a2 = fA[tx + 32], a3 = fA[tx + 48];
            float b0 = fB[tx], b1 = fB[tx + 16], b2 = fB[tx + 32], b3 = fB[tx + 48];
#pragma unroll
            for (int i = 0; i < 8; ++i) {
                int c = r0 - 64 + i;
                float uc = us[c], rc = rbs[c];
                float* orow = catb + (size_t)c * NPIX + pb + tx;
                orow[0]  = fmaf(b0, accs[i][0], fmaf(a0, uc, rc));
                orow[16] = fmaf(b1, accs[i][1], fmaf(a1, uc, rc));
                orow[32] = fmaf(b2, accs[i][2], fmaf(a2, uc, rc));
                orow[48] = fmaf(b3, accs[i][3], fmaf(a3, uc, rc));
            }
        }
    }
}

// ===========================================================================
// conv: 3x3 SAME 128->64. grid (16, 64, 8) x 256. Block: 64 oc x (16w x 4h).
// Thread: 4 oc x 4 y at one x. Packed over ic (pairs).
// ===========================================================================
__global__ __launch_bounds__(256) void conv_kernel(
    const float* __restrict__ cb, float* __restrict__ out)
{
    __shared__ __align__(16) float ws[9216];
    __shared__ __align__(16) float is2[1728];

    const int x0 = blockIdx.x * 16;
    const int y0 = blockIdx.y * 4;
    const int b  = blockIdx.z;
    const int t  = threadIdx.x;
    const int pxg = t & 15;
    const int ocg = t >> 4;

    u64 acc2[4][4];
#pragma unroll
    for (int i = 0; i < 4; ++i)
#pragma unroll
        for (int j = 0; j < 4; ++j) acc2[i][j] = 0ULL;

    const float* catb = g_cat + (size_t)b * 128 * NPIX;

    for (int ch = 0; ch < 8; ++ch) {
        const int ic0 = ch * 16;     // icp0 = ch*8
        __syncthreads();
        for (int e = t; e < 9216; e += 256) {
            int kk = e >> 10, rem = e & 1023;
            ws[e] = g_wt[(size_t)kk * 8192 + (size_t)(ch * 8) * 128 + rem];
        }
        for (int e = t; e < 1728; e += 256) {
            int ic = e / 108, pos = e - ic * 108;
            int yy = pos / 18, xx = pos - yy * 18;
            int gy = y0 - 1 + yy, gx = x0 - 1 + xx;
            float v = 0.f;
            if ((unsigned)gy < 256u && (unsigned)gx < 256u)
                v = catb[((size_t)(ic0 + ic) << 16) + gy * 256 + gx];
            is2[(ic >> 1) * 216 + pos * 2 + (ic & 1)] = v;
        }
        __syncthreads();

#pragma unroll 2
        for (int il = 0; il < 8; ++il) {
            u64 rin[6][3];
            const float* ib = &is2[il * 216 + pxg * 2];
#pragma unroll
            for (int rr = 0; rr < 6; ++rr)
#pragma unroll
                for (int dx = 0; dx < 3; ++dx)
                    rin[rr][dx] = *reinterpret_cast<const u64*>(ib + (rr * 18 + dx) * 2);
#pragma unroll
            for (int ky = 0; ky < 3; ++ky)
#pragma unroll
                for (int kx = 0; kx < 3; ++kx) {
                    const ulonglong2* wp = reinterpret_cast<const ulonglong2*>(
                        &ws[(ky * 3 + kx) * 1024 + il * 128 + ocg * 8]);
                    ulonglong2 W0 = wp[0], W1 = wp[1];
                    u64 w4[4] = {W0.x, W0.y, W1.x, W1.y};
#pragma unroll
                    for (int yy = 0; yy < 4; ++yy) {
                        u64 iv = rin[yy + ky][kx];
                        fma2(acc2[0][yy], w4[0], iv);
                        fma2(acc2[1][yy], w4[1], iv);
                        fma2(acc2[2][yy], w4[2], iv);
                        fma2(acc2[3][yy], w4[3], iv);
                    }
                }
        }
    }

#pragma unroll
    for (int i = 0; i < 4; ++i) {
        int oc = ocg * 4 + i;
        float bias = cb[oc];
#pragma unroll
        for (int yy = 0; yy < 4; ++yy)
            out[((size_t)(b * 64 + oc) << 16) + (size_t)(y0 + yy) * 256 + x0 + pxg] =
                hsum2(acc2[i][yy]) + bias;
    }
}

// ===========================================================================
extern "C" void kernel_launch(void* const* d_in, const int* in_sizes, int n_in,
                              void* d_out, int out_size)
{
    (void)in_sizes; (void)n_in; (void)out_size;
    const float* t1  = (const float*)d_in[0];
    const float* t2  = (const float*)d_in[1];
    const float* q1w = (const float*)d_in[2];
    const float* q1b = (const float*)d_in[3];
    const float* k1w = (const float*)d_in[4];
    const float* k1b = (const float*)d_in[5];
    const float* v1w = (const float*)d_in[6];
    const float* v1b = (const float*)d_in[7];
    const float* r1w = (const float*)d_in[8];
    const float* r1b = (const float*)d_in[9];
    const float* q2w = (const float*)d_in[10];
    const float* q2b = (const float*)d_in[11];
    const float* k2w = (const float*)d_in[12];
    const float* k2b = (const float*)d_in[13];
    const float* v2w = (const float*)d_in[14];
    const float* v2b = (const float*)d_in[15];
    const float* r2w = (const float*)d_in[16];
    const float* r2b = (const float*)d_in[17];
    const float* cw  = (const float*)d_in[18];
    const float* cbp = (const float*)d_in[19];
    float* out = (float*)d_out;

    cudaFuncSetAttribute(pass1_kernel, cudaFuncAttributeMaxDynamicSharedMemorySize, 90 * 1024);
    cudaFuncSetAttribute(pass2_kernel, cudaFuncAttributeMaxDynamicSharedMemorySize, 60 * 1024);

    wt_kernel<<<288, 256>>>(cw);
    pass1_kernel<<<dim3(64, 8, 2), 256, 88320>>>(t1, t2, k1w, k1b, v1w, v1b,
                                                 k2w, k2b, v2w, v2b);
    prep_kernel<<<16, 256>>>(q1w, q1b, r1w, q2w, q2b, r2w);
    pass2_kernel<<<dim3(64, 8, 2), 256, 56576>>>(t1, t2, r1b, r2b);
    conv_kernel<<<dim3(16, 64, 8), 256>>>(cbp, out);
}